// round 13
// baseline (speedup 1.0000x reference)
#include <cuda_runtime.h>
#include <cuda_bf16.h>
#include <math.h>
#include <stdint.h>

#define NTOK 65536

// ---------------- scratch ----------------
__device__ __nv_bfloat16 g_xw  [(size_t)NTOK * 192];
__device__ __nv_bfloat16 g_qkv [(size_t)NTOK * 576];
__device__ __nv_bfloat16 g_attn[(size_t)NTOK * 192];
__device__ float         g_xo  [(size_t)NTOK * 192];
__device__ __nv_bfloat16 g_xn2 [(size_t)NTOK * 192];
__device__ __nv_bfloat16 g_h1  [(size_t)NTOK * 768];
__device__ __nv_bfloat16 g_wqkvt[576 * 192];
__device__ __nv_bfloat16 g_wot  [192 * 192];
__device__ __nv_bfloat16 g_w1t  [768 * 192];
__device__ __nv_bfloat16 g_w2t  [192 * 768];
__device__ __nv_bfloat16 g_bm   [6 * 8 * 64 * 64];

// ---------------- helpers ----------------
__device__ __forceinline__ uint32_t smem_u32(const void* p) {
    uint32_t a;
    asm("{ .reg .u64 t; cvta.to.shared.u64 t, %1; cvt.u32.u64 %0, t; }" : "=r"(a) : "l"(p));
    return a;
}
__device__ __forceinline__ void ldsm_x4(uint32_t* r, uint32_t addr) {
    asm volatile("ldmatrix.sync.aligned.m8n8.x4.shared.b16 {%0,%1,%2,%3}, [%4];"
                 : "=r"(r[0]), "=r"(r[1]), "=r"(r[2]), "=r"(r[3]) : "r"(addr));
}
__device__ __forceinline__ void ldsm_x4t(uint32_t* r, uint32_t addr) {
    asm volatile("ldmatrix.sync.aligned.m8n8.x4.trans.shared.b16 {%0,%1,%2,%3}, [%4];"
                 : "=r"(r[0]), "=r"(r[1]), "=r"(r[2]), "=r"(r[3]) : "r"(addr));
}
__device__ __forceinline__ void mma_bf16(float* c, const uint32_t* a,
                                         uint32_t b0, uint32_t b1) {
    asm volatile(
        "mma.sync.aligned.m16n8k16.row.col.f32.bf16.bf16.f32 "
        "{%0,%1,%2,%3}, {%4,%5,%6,%7}, {%8,%9}, {%0,%1,%2,%3};"
        : "+f"(c[0]), "+f"(c[1]), "+f"(c[2]), "+f"(c[3])
        : "r"(a[0]), "r"(a[1]), "r"(a[2]), "r"(a[3]), "r"(b0), "r"(b1));
}
__device__ __forceinline__ uint32_t pack_bf16(float x, float y) {
    uint32_t r;
    asm("cvt.rn.bf16x2.f32 %0, %1, %2;" : "=r"(r) : "f"(y), "f"(x));
    return r;
}
__device__ __forceinline__ float2 bf2f(uint32_t u) {
    __nv_bfloat162 h = *reinterpret_cast<__nv_bfloat162*>(&u);
    return __bfloat1622float2(h);
}
__device__ __forceinline__ void cpa16(uint32_t dst, const void* src) {
    asm volatile("cp.async.cg.shared.global [%0], [%1], 16;" :: "r"(dst), "l"(src));
}

// ---------------- prep: weight transpose (0..431) + bias+mask (432..1199) ------
__global__ __launch_bounds__(256)
void prep_kernel(const float* __restrict__ wa, __nv_bfloat16* __restrict__ oa,
                 const float* __restrict__ wb, __nv_bfloat16* __restrict__ ob,
                 const float* __restrict__ wc, __nv_bfloat16* __restrict__ oc,
                 const float* __restrict__ wd, __nv_bfloat16* __restrict__ od,
                 const float* __restrict__ bt, __nv_bfloat16* __restrict__ bm)
{
    const int bid = blockIdx.x;
    const int tid = threadIdx.x;
    if (bid >= 432) {
        const int e = (bid - 432) * 256 + tid;
        const int j = e & 63, i = (e >> 6) & 63, t = (e >> 12) & 7, h = e >> 15;
        const int idx = ((i >> 4) - (j >> 4) + 3) * 49
                      + (((i >> 2) & 3) - ((j >> 2) & 3) + 3) * 7
                      + ((i & 3) - (j & 3) + 3);
        const float bias = bt[idx * 6 + h];
        const int bh = (t >> 2) & 1, bw = (t >> 1) & 1, bd = t & 1;
        const int gi = (bh ? (((i >> 4) < 2) ? 1 : 2) : 0) * 9
                     + (bw ? ((((i >> 2) & 3) < 2) ? 1 : 2) : 0) * 3
                     + (bd ? (((i & 3) < 2) ? 1 : 2) : 0);
        const int gj = (bh ? (((j >> 4) < 2) ? 1 : 2) : 0) * 9
                     + (bw ? ((((j >> 2) & 3) < 2) ? 1 : 2) : 0) * 3
                     + (bd ? (((j & 3) < 2) ? 1 : 2) : 0);
        bm[e] = __float2bfloat16(bias + ((gi == gj) ? 0.f : -100.f));
        return;
    }
    __shared__ float t[32][33];
    const float* in; __nv_bfloat16* out; int K, N, tile;
    if (bid < 108)      { in = wa; out = oa; K = 192; N = 576; tile = bid; }
    else if (bid < 144) { in = wb; out = ob; K = 192; N = 192; tile = bid - 108; }
    else if (bid < 288) { in = wc; out = oc; K = 192; N = 768; tile = bid - 144; }
    else                { in = wd; out = od; K = 768; N = 192; tile = bid - 288; }
    const int kt = tile % (K >> 5), nt = tile / (K >> 5);
    const int k0 = kt << 5, n0 = nt << 5;
    const int tx = tid & 31, ty = tid >> 5;
#pragma unroll
    for (int i = 0; i < 32; i += 8)
        t[ty + i][tx] = in[(size_t)(k0 + ty + i) * N + n0 + tx];
    __syncthreads();
#pragma unroll
    for (int i = 0; i < 32; i += 8)
        out[(size_t)(n0 + ty + i) * K + k0 + tx] = __float2bfloat16(t[tx][ty + i]);
}

// ---------------- LayerNorm1 + shift + window partition ------------------------
__global__ __launch_bounds__(256)
void ln_kernel(const float* __restrict__ x, const float* __restrict__ g,
               const float* __restrict__ b, __nv_bfloat16* __restrict__ out)
{
    const int t = blockIdx.x * 8 + (threadIdx.x >> 5);
    const int lane = threadIdx.x & 31;
    const int b_ = t >> 6, n = t & 63;
    const int bb = b_ >> 9, widx = b_ & 511;
    const int hs = ((widx >> 6) << 2) + (n >> 4);
    const int ws = (((widx >> 3) & 7) << 2) + ((n >> 2) & 3);
    const int ds = ((widx & 7) << 2) + (n & 3);
    const size_t src = ((((size_t)bb * 32 + ((hs + 2) & 31)) * 32 + ((ws + 2) & 31)) * 32
                       + ((ds + 2) & 31));
    const float* xp = x + src * 192;
    float v[6];
    float s = 0.f;
#pragma unroll
    for (int r = 0; r < 6; ++r) { v[r] = xp[lane + 32 * r]; s += v[r]; }
#pragma unroll
    for (int o = 16; o > 0; o >>= 1) s += __shfl_xor_sync(0xffffffffu, s, o);
    const float mean = s * (1.f / 192.f);
    float vv = 0.f;
#pragma unroll
    for (int r = 0; r < 6; ++r) { const float d = v[r] - mean; vv += d * d; }
#pragma unroll
    for (int o = 16; o > 0; o >>= 1) vv += __shfl_xor_sync(0xffffffffu, vv, o);
    const float rstd = rsqrtf(vv * (1.f / 192.f) + 1e-5f);
    __nv_bfloat16* op = out + (size_t)t * 192;
#pragma unroll
    for (int r = 0; r < 6; ++r) {
        const int c = lane + 32 * r;
        op[c] = __float2bfloat16((v[r] - mean) * rstd * g[c] + b[c]);
    }
}

// ---------------- bf16 GEMM: BM=64, BN=192, BK=64, 2-stage, compile-time K -----
#define GSM_A 9216
#define GSM_B 27648
#define GSM_ST (GSM_A + GSM_B)
#define GSM_TOT (2 * GSM_ST)

template <int EPI, int KD>
__global__ __launch_bounds__(256, 3)
void mma_gemm(const __nv_bfloat16* __restrict__ A, const __nv_bfloat16* __restrict__ Bt,
              const float* __restrict__ bias, void* __restrict__ Cv,
              int ldc, const float* __restrict__ resid,
              const float* __restrict__ lg, const float* __restrict__ lb,
              __nv_bfloat16* __restrict__ xn2)
{
    constexpr bool OBF = (EPI == 0 || EPI == 1);
    constexpr int NC = KD >> 6;
    extern __shared__ __align__(16) uint8_t dsm[];
    __shared__ float2 red[64][4];

    const int tid = threadIdx.x;
    const int warp = tid >> 5, lane = tid & 31;
    const int m0 = blockIdx.y << 6;
    const int n0 = blockIdx.x * 192;
    const int mwarp = (warp & 1) << 5;
    const int nwarp = (warp >> 1) * 48;
    const uint32_t sb = smem_u32(dsm);
    const int lrow = lane & 15, lkh = lane >> 4;

    auto issue = [&](int c) {
        if (c < NC) {
            const uint32_t ab = sb + (c & 1) * GSM_ST;
            const uint32_t bb = ab + GSM_A;
            const int kc = c << 6;
#pragma unroll
            for (int i = 0; i < 2; ++i) {
                const int idx = i * 256 + tid;
                const int row = idx >> 3, seg = idx & 7;
                cpa16(ab + row * 144 + seg * 16,
                      A + (size_t)(m0 + row) * KD + kc + seg * 8);
            }
#pragma unroll
            for (int i = 0; i < 6; ++i) {
                const int idx = i * 256 + tid;
                const int row = idx >> 3, seg = idx & 7;
                cpa16(bb + row * 144 + seg * 16,
                      Bt + (size_t)(n0 + row) * KD + kc + seg * 8);
            }
        }
        asm volatile("cp.async.commit_group;" ::: "memory");
    };

    float acc[2][6][4];
#pragma unroll
    for (int i = 0; i < 2; ++i)
#pragma unroll
        for (int j = 0; j < 6; ++j)
#pragma unroll
            for (int e = 0; e < 4; ++e) acc[i][j][e] = 0.f;

    issue(0);
#pragma unroll
    for (int c = 0; c < NC; ++c) {
        asm volatile("cp.async.wait_group 0;" ::: "memory");
        __syncthreads();
        issue(c + 1);
        const uint32_t ab = sb + (c & 1) * GSM_ST;
        const uint32_t bb = ab + GSM_A;
#pragma unroll
        for (int kk = 0; kk < 4; ++kk) {
            uint32_t a[2][4], b[3][4];
#pragma unroll
            for (int mi = 0; mi < 2; ++mi)
                ldsm_x4(a[mi], ab + (mwarp + mi * 16 + lrow) * 144 + kk * 32 + lkh * 16);
#pragma unroll
            for (int ng = 0; ng < 3; ++ng)
                ldsm_x4(b[ng], bb + (nwarp + ng * 16 + lrow) * 144 + kk * 32 + lkh * 16);
#pragma unroll
            for (int mi = 0; mi < 2; ++mi)
#pragma unroll
                for (int nj = 0; nj < 6; ++nj)
                    mma_bf16(acc[mi][nj], a[mi],
                             b[nj >> 1][nj & 1], b[nj >> 1][(nj & 1) + 2]);
        }
    }

    const int g = lane >> 2, t2 = (lane & 3) * 2;

    if (EPI == 2) {
        size_t tds[2][2];
#pragma unroll
        for (int mi = 0; mi < 2; ++mi) {
#pragma unroll
            for (int half = 0; half < 2; ++half) {
                const int r = mwarp + mi * 16 + g + half * 8;
                const int m = m0 + r;
                const int b_ = m >> 6, n = m & 63;
                const int bb2 = b_ >> 9, widx = b_ & 511;
                const int hs = ((widx >> 6) << 2) + (n >> 4);
                const int ws = (((widx >> 3) & 7) << 2) + ((n >> 2) & 3);
                const int ds = ((widx & 7) << 2) + (n & 3);
                const size_t td = ((((size_t)bb2 * 32 + ((hs + 2) & 31)) * 32
                                   + ((ws + 2) & 31)) * 32 + ((ds + 2) & 31));
                tds[mi][half] = td;
                float s = 0.f, sq = 0.f;
#pragma unroll
                for (int nj = 0; nj < 6; ++nj) {
                    const int col = nwarp + nj * 8 + t2;
                    const float2 bv = *(const float2*)(bias + col);
                    const float2 rv = *(const float2*)(resid + td * 192 + col);
                    float ox = acc[mi][nj][half * 2 + 0] + bv.x + rv.x;
                    float oy = acc[mi][nj][half * 2 + 1] + bv.y + rv.y;
                    acc[mi][nj][half * 2 + 0] = ox;
                    acc[mi][nj][half * 2 + 1] = oy;
                    *(float2*)((float*)Cv + td * 192 + col) = make_float2(ox, oy);
                    s += ox + oy;
                    sq += ox * ox + oy * oy;
                }
                s  += __shfl_xor_sync(0xffffffffu, s, 1);
                s  += __shfl_xor_sync(0xffffffffu, s, 2);
                sq += __shfl_xor_sync(0xffffffffu, sq, 1);
                sq += __shfl_xor_sync(0xffffffffu, sq, 2);
                if ((lane & 3) == 0) red[r][warp >> 1] = make_float2(s, sq);
            }
        }
        __syncthreads();
#pragma unroll
        for (int mi = 0; mi < 2; ++mi) {
#pragma unroll
            for (int half = 0; half < 2; ++half) {
                const int r = mwarp + mi * 16 + g + half * 8;
                const float2 r0 = red[r][0], r1 = red[r][1];
                const float2 r2 = red[r][2], r3 = red[r][3];
                const float s = r0.x + r1.x + r2.x + r3.x;
                const float sq = r0.y + r1.y + r2.y + r3.y;
                const float mean = s * (1.f / 192.f);
                const float var = sq * (1.f / 192.f) - mean * mean;
                const float rstd = rsqrtf(var + 1e-5f);
                const size_t td = tds[mi][half];
#pragma unroll
                for (int nj = 0; nj < 6; ++nj) {
                    const int col = nwarp + nj * 8 + t2;
                    const float2 gv = *(const float2*)(lg + col);
                    const float2 bv2 = *(const float2*)(lb + col);
                    const float vx = (acc[mi][nj][half * 2 + 0] - mean) * rstd * gv.x + bv2.x;
                    const float vy = (acc[mi][nj][half * 2 + 1] - mean) * rstd * gv.y + bv2.y;
                    *(uint32_t*)(xn2 + td * 192 + col) = pack_bf16(vx, vy);
                }
            }
        }
        return;
    }

#pragma unroll
    for (int mi = 0; mi < 2; ++mi) {
#pragma unroll
        for (int half = 0; half < 2; ++half) {
            const int m = m0 + mwarp + mi * 16 + g + half * 8;
#pragma unroll
            for (int nj = 0; nj < 6; ++nj) {
                const int col = n0 + nwarp + nj * 8 + t2;
                const float2 bv = *(const float2*)(bias + col);
                float ox = acc[mi][nj][half * 2 + 0] + bv.x;
                float oy = acc[mi][nj][half * 2 + 1] + bv.y;
                if (EPI == 1) {
                    const float kk = 0.70710678118654752f;
                    ox = 0.5f * ox * (1.f + erff(ox * kk));
                    oy = 0.5f * oy * (1.f + erff(oy * kk));
                }
                if (EPI == 3) {
                    const float2 rv = *(const float2*)(resid + (size_t)m * 192 + col);
                    ox += rv.x; oy += rv.y;
                }
                if (OBF) {
                    *(uint32_t*)((__nv_bfloat16*)Cv + (size_t)m * ldc + col) = pack_bf16(ox, oy);
                } else {
                    *(float2*)((float*)Cv + (size_t)m * ldc + col) = make_float2(ox, oy);
                }
            }
        }
    }
}

// ---------------- windowed attention: Q direct from gmem, K/V in smem ----------
__global__ __launch_bounds__(256)
void attn_kernel(const __nv_bfloat16* __restrict__ qkv, const __nv_bfloat16* __restrict__ bm,
                 __nv_bfloat16* __restrict__ out)
{
    __shared__ __align__(16) uint8_t ks[64 * 144];
    __shared__ __align__(16) uint8_t vs[64 * 144];

    const int tid = threadIdx.x;
    const int wnd = blockIdx.x & 1023;
    const int hb = (blockIdx.x >> 10) << 1;
    const int widx = wnd & 511;
    const int wtype = (((widx >> 6) == 7) << 2) | ((((widx >> 3) & 7) == 7) << 1)
                    | ((widx & 7) == 7);

    {
        const int r = tid >> 2, s4 = tid & 3;
        const __nv_bfloat16* tp = qkv + ((size_t)wnd * 64 + r) * 576 + hb * 32;
        *(uint4*)(ks + r * 144 + s4 * 16)       = *(const uint4*)(tp + 192 + s4 * 8);
        *(uint4*)(ks + r * 144 + s4 * 16 + 64)  = *(const uint4*)(tp + 192 + s4 * 8 + 32);
        *(uint4*)(vs + r * 144 + s4 * 16)       = *(const uint4*)(tp + 384 + s4 * 8);
        *(uint4*)(vs + r * 144 + s4 * 16 + 64)  = *(const uint4*)(tp + 384 + s4 * 8 + 32);
    }
    __syncthreads();

    const int warp = tid >> 5, lane = tid & 31;
    const int lrow = lane & 15, lkh = lane >> 4;
    const int g = lane >> 2, t2 = (lane & 3) * 2;
    const int h = hb + (warp >> 2);
    const int hoff = (warp >> 2) * 64;        // byte offset in ks/vs rows
    const int msl = (warp & 3) * 16;
    const uint32_t ks_b = smem_u32(ks), vs_b = smem_u32(vs);
    const float scl = 0.17677669529663687f;

    // Q fragment pointers (direct gmem): rows msl+g / msl+g+8, head h
    const __nv_bfloat16* q0 = qkv + ((size_t)wnd * 64 + msl + g) * 576 + h * 32 + t2;
    const __nv_bfloat16* q1 = q0 + 8 * 576;

    float acc[8][4];
#pragma unroll
    for (int nj = 0; nj < 8; ++nj)
#pragma unroll
        for (int e = 0; e < 4; ++e) acc[nj][e] = 0.f;
#pragma unroll
    for (int kk = 0; kk < 2; ++kk) {
        uint32_t a[4];
        a[0] = *(const uint32_t*)(q0 + kk * 16);
        a[1] = *(const uint32_t*)(q1 + kk * 16);
        a[2] = *(const uint32_t*)(q0 + kk * 16 + 8);
        a[3] = *(const uint32_t*)(q1 + kk * 16 + 8);
#pragma unroll
        for (int ng = 0; ng < 4; ++ng) {
            uint32_t b[4];
            ldsm_x4(b, ks_b + (ng * 16 + lrow) * 144 + hoff + kk * 32 + lkh * 16);
            mma_bf16(acc[2 * ng],     a, b[0], b[2]);
            mma_bf16(acc[2 * ng + 1], a, b[1], b[3]);
        }
    }

    const int i0 = msl + g, i1 = i0 + 8;
    const __nv_bfloat16* bmp = bm + ((((size_t)h << 3) + wtype) << 12);
#pragma unroll
    for (int nj = 0; nj < 8; ++nj) {
        const int j = nj * 8 + t2;
        const float2 f0 = bf2f(*(const uint32_t*)(bmp + (i0 << 6) + j));
        const float2 f1 = bf2f(*(const uint32_t*)(bmp + (i1 << 6) + j));
        acc[nj][0] = fmaf(acc[nj][0], scl, f0.x);
        acc[nj][1] = fmaf(acc[nj][1], scl, f0.y);
        acc[nj][2] = fmaf(acc[nj][2], scl, f1.x);
        acc[nj][3] = fmaf(acc[nj][3], scl, f1.y);
    }

    float mx0 = -1e30f, mx1 = -1e30f;
#pragma unroll
    for (int nj = 0; nj < 8; ++nj) {
        mx0 = fmaxf(mx0, fmaxf(acc[nj][0], acc[nj][1]));
        mx1 = fmaxf(mx1, fmaxf(acc[nj][2], acc[nj][3]));
    }
    mx0 = fmaxf(mx0, __shfl_xor_sync(0xffffffffu, mx0, 1));
    mx0 = fmaxf(mx0, __shfl_xor_sync(0xffffffffu, mx0, 2));
    mx1 = fmaxf(mx1, __shfl_xor_sync(0xffffffffu, mx1, 1));
    mx1 = fmaxf(mx1, __shfl_xor_sync(0xffffffffu, mx1, 2));
    float s0 = 0.f, s1 = 0.f;
#pragma unroll
    for (int nj = 0; nj < 8; ++nj) {
        acc[nj][0] = __expf(acc[nj][0] - mx0); s0 += acc[nj][0];
        acc[nj][1] = __expf(acc[nj][1] - mx0); s0 += acc[nj][1];
        acc[nj][2] = __expf(acc[nj][2] - mx1); s1 += acc[nj][2];
        acc[nj][3] = __expf(acc[nj][3] - mx1); s1 += acc[nj][3];
    }
    s0 += __shfl_xor_sync(0xffffffffu, s0, 1);
    s0 += __shfl_xor_sync(0xffffffffu, s0, 2);
    s1 += __shfl_xor_sync(0xffffffffu, s1, 1);
    s1 += __shfl_xor_sync(0xffffffffu, s1, 2);
    const float r0 = 1.f / s0, r1 = 1.f / s1;

    uint32_t pa[4][4];
#pragma unroll
    for (int kc = 0; kc < 4; ++kc) {
        pa[kc][0] = pack_bf16(acc[2 * kc][0] * r0,     acc[2 * kc][1] * r0);
        pa[kc][1] = pack_bf16(acc[2 * kc][2] * r1,     acc[2 * kc][3] * r1);
        pa[kc][2] = pack_bf16(acc[2 * kc + 1][0] * r0, acc[2 * kc + 1][1] * r0);
        pa[kc][3] = pack_bf16(acc[2 * kc + 1][2] * r1, acc[2 * kc + 1][3] * r1);
    }
    float o[4][4];
#pragma unroll
    for (int dj = 0; dj < 4; ++dj)
#pragma unroll
        for (int e = 0; e < 4; ++e) o[dj][e] = 0.f;
#pragma unroll
    for (int kc = 0; kc < 4; ++kc) {
#pragma unroll
        for (int dt = 0; dt < 2; ++dt) {
            uint32_t b[4];
            ldsm_x4t(b, vs_b + (kc * 16 + lrow) * 144 + hoff + dt * 32 + lkh * 16);
            mma_bf16(o[2 * dt],     pa[kc], b[0], b[1]);
            mma_bf16(o[2 * dt + 1], pa[kc], b[2], b[3]);
        }
    }

#pragma unroll
    for (int dj = 0; dj < 4; ++dj) {
        const int d = dj * 8 + t2;
        __nv_bfloat16* op0 = out + ((size_t)wnd * 64 + i0) * 192 + h * 32 + d;
        *(uint32_t*)op0             = pack_bf16(o[dj][0], o[dj][1]);
        *(uint32_t*)(op0 + 8 * 192) = pack_bf16(o[dj][2], o[dj][3]);
    }
}

// ---------------- launch --------------------------------------------------------
extern "C" void kernel_launch(void* const* d_in, const int* in_sizes, int n_in,
                              void* d_out, int out_size)
{
    const float* x    = (const float*)d_in[0];
    const float* g1   = (const float*)d_in[1];
    const float* b1   = (const float*)d_in[2];
    const float* wqkv = (const float*)d_in[3];
    const float* bqkv = (const float*)d_in[4];
    const float* wo   = (const float*)d_in[5];
    const float* bo   = (const float*)d_in[6];
    const float* bt   = (const float*)d_in[7];
    const float* g2   = (const float*)d_in[8];
    const float* b2   = (const float*)d_in[9];
    const float* w1   = (const float*)d_in[10];
    const float* bm1  = (const float*)d_in[11];
    const float* w2   = (const float*)d_in[12];
    const float* bm2  = (const float*)d_in[13];
    float* out = (float*)d_out;

    __nv_bfloat16 *p_xw, *p_qkv, *p_attn, *p_xn2, *p_h1, *p_bm;
    __nv_bfloat16 *p_wqkvt, *p_wot, *p_w1t, *p_w2t;
    float *p_xo;
    cudaGetSymbolAddress((void**)&p_xw,    g_xw);
    cudaGetSymbolAddress((void**)&p_qkv,   g_qkv);
    cudaGetSymbolAddress((void**)&p_attn,  g_attn);
    cudaGetSymbolAddress((void**)&p_xo,    g_xo);
    cudaGetSymbolAddress((void**)&p_xn2,   g_xn2);
    cudaGetSymbolAddress((void**)&p_h1,    g_h1);
    cudaGetSymbolAddress((void**)&p_wqkvt, g_wqkvt);
    cudaGetSymbolAddress((void**)&p_wot,   g_wot);
    cudaGetSymbolAddress((void**)&p_w1t,   g_w1t);
    cudaGetSymbolAddress((void**)&p_w2t,   g_w2t);
    cudaGetSymbolAddress((void**)&p_bm,    g_bm);

    cudaFuncSetAttribute((const void*)mma_gemm<0,192>, cudaFuncAttributeMaxDynamicSharedMemorySize, GSM_TOT);
    cudaFuncSetAttribute((const void*)mma_gemm<1,192>, cudaFuncAttributeMaxDynamicSharedMemorySize, GSM_TOT);
    cudaFuncSetAttribute((const void*)mma_gemm<2,192>, cudaFuncAttributeMaxDynamicSharedMemorySize, GSM_TOT);
    cudaFuncSetAttribute((const void*)mma_gemm<3,768>, cudaFuncAttributeMaxDynamicSharedMemorySize, GSM_TOT);

    prep_kernel<<<1200, 256>>>(wqkv, p_wqkvt, wo, p_wot, w1, p_w1t, w2, p_w2t, bt, p_bm);
    ln_kernel<<<NTOK / 8, 256>>>(x, g1, b1, p_xw);
    mma_gemm<0,192><<<dim3(3, NTOK / 64), 256, GSM_TOT>>>(p_xw, p_wqkvt, bqkv, p_qkv,
                                                          576, nullptr, nullptr, nullptr, nullptr);
    attn_kernel<<<3072, 256>>>(p_qkv, p_bm, p_attn);
    mma_gemm<2,192><<<dim3(1, NTOK / 64), 256, GSM_TOT>>>(p_attn, p_wot, bo, p_xo,
                                                          192, x, g2, b2, p_xn2);
    mma_gemm<1,192><<<dim3(4, NTOK / 64), 256, GSM_TOT>>>(p_xn2, p_w1t, bm1, p_h1,
                                                          768, nullptr, nullptr, nullptr, nullptr);
    mma_gemm<3,768><<<dim3(1, NTOK / 64), 256, GSM_TOT>>>(p_h1, p_w2t, bm2, out,
                                                          192, p_xo, nullptr, nullptr, nullptr);
}

// round 14
// speedup vs baseline: 1.2857x; 1.2857x over previous
#include <cuda_runtime.h>
#include <cuda_bf16.h>
#include <math.h>
#include <stdint.h>

#define NTOK 65536

// ---------------- scratch ----------------
__device__ __nv_bfloat16 g_xw  [(size_t)NTOK * 192];
__device__ __nv_bfloat16 g_qkv [(size_t)NTOK * 576];
__device__ __nv_bfloat16 g_attn[(size_t)NTOK * 192];
__device__ float         g_xo  [(size_t)NTOK * 192];
__device__ __nv_bfloat16 g_xn2 [(size_t)NTOK * 192];
__device__ __nv_bfloat16 g_h1  [(size_t)NTOK * 768];
__device__ __nv_bfloat16 g_wqkvt[576 * 192];
__device__ __nv_bfloat16 g_wot  [192 * 192];
__device__ __nv_bfloat16 g_w1t  [768 * 192];
__device__ __nv_bfloat16 g_w2t  [192 * 768];
__device__ __nv_bfloat16 g_bm   [6 * 8 * 64 * 64];

// ---------------- helpers ----------------
__device__ __forceinline__ uint32_t smem_u32(const void* p) {
    uint32_t a;
    asm("{ .reg .u64 t; cvta.to.shared.u64 t, %1; cvt.u32.u64 %0, t; }" : "=r"(a) : "l"(p));
    return a;
}
__device__ __forceinline__ void ldsm_x4(uint32_t* r, uint32_t addr) {
    asm volatile("ldmatrix.sync.aligned.m8n8.x4.shared.b16 {%0,%1,%2,%3}, [%4];"
                 : "=r"(r[0]), "=r"(r[1]), "=r"(r[2]), "=r"(r[3]) : "r"(addr));
}
__device__ __forceinline__ void ldsm_x4t(uint32_t* r, uint32_t addr) {
    asm volatile("ldmatrix.sync.aligned.m8n8.x4.trans.shared.b16 {%0,%1,%2,%3}, [%4];"
                 : "=r"(r[0]), "=r"(r[1]), "=r"(r[2]), "=r"(r[3]) : "r"(addr));
}
__device__ __forceinline__ void mma_bf16(float* c, const uint32_t* a,
                                         uint32_t b0, uint32_t b1) {
    asm volatile(
        "mma.sync.aligned.m16n8k16.row.col.f32.bf16.bf16.f32 "
        "{%0,%1,%2,%3}, {%4,%5,%6,%7}, {%8,%9}, {%0,%1,%2,%3};"
        : "+f"(c[0]), "+f"(c[1]), "+f"(c[2]), "+f"(c[3])
        : "r"(a[0]), "r"(a[1]), "r"(a[2]), "r"(a[3]), "r"(b0), "r"(b1));
}
__device__ __forceinline__ uint32_t pack_bf16(float x, float y) {
    uint32_t r;
    asm("cvt.rn.bf16x2.f32 %0, %1, %2;" : "=r"(r) : "f"(y), "f"(x));
    return r;
}
__device__ __forceinline__ float2 bf2f(uint32_t u) {
    __nv_bfloat162 h = *reinterpret_cast<__nv_bfloat162*>(&u);
    return __bfloat1622float2(h);
}
__device__ __forceinline__ void cpa16(uint32_t dst, const void* src) {
    asm volatile("cp.async.cg.shared.global [%0], [%1], 16;" :: "r"(dst), "l"(src));
}

// ---------------- prep: weight transpose (0..431) + bias+mask (432..1199) ------
__global__ __launch_bounds__(256)
void prep_kernel(const float* __restrict__ wa, __nv_bfloat16* __restrict__ oa,
                 const float* __restrict__ wb, __nv_bfloat16* __restrict__ ob,
                 const float* __restrict__ wc, __nv_bfloat16* __restrict__ oc,
                 const float* __restrict__ wd, __nv_bfloat16* __restrict__ od,
                 const float* __restrict__ bt, __nv_bfloat16* __restrict__ bm)
{
    const int bid = blockIdx.x;
    const int tid = threadIdx.x;
    if (bid >= 432) {
        const int e = (bid - 432) * 256 + tid;
        const int j = e & 63, i = (e >> 6) & 63, t = (e >> 12) & 7, h = e >> 15;
        const int idx = ((i >> 4) - (j >> 4) + 3) * 49
                      + (((i >> 2) & 3) - ((j >> 2) & 3) + 3) * 7
                      + ((i & 3) - (j & 3) + 3);
        const float bias = bt[idx * 6 + h];
        const int bh = (t >> 2) & 1, bw = (t >> 1) & 1, bd = t & 1;
        const int gi = (bh ? (((i >> 4) < 2) ? 1 : 2) : 0) * 9
                     + (bw ? ((((i >> 2) & 3) < 2) ? 1 : 2) : 0) * 3
                     + (bd ? (((i & 3) < 2) ? 1 : 2) : 0);
        const int gj = (bh ? (((j >> 4) < 2) ? 1 : 2) : 0) * 9
                     + (bw ? ((((j >> 2) & 3) < 2) ? 1 : 2) : 0) * 3
                     + (bd ? (((j & 3) < 2) ? 1 : 2) : 0);
        bm[e] = __float2bfloat16(bias + ((gi == gj) ? 0.f : -100.f));
        return;
    }
    __shared__ float t[32][33];
    const float* in; __nv_bfloat16* out; int K, N, tile;
    if (bid < 108)      { in = wa; out = oa; K = 192; N = 576; tile = bid; }
    else if (bid < 144) { in = wb; out = ob; K = 192; N = 192; tile = bid - 108; }
    else if (bid < 288) { in = wc; out = oc; K = 192; N = 768; tile = bid - 144; }
    else                { in = wd; out = od; K = 768; N = 192; tile = bid - 288; }
    const int kt = tile % (K >> 5), nt = tile / (K >> 5);
    const int k0 = kt << 5, n0 = nt << 5;
    const int tx = tid & 31, ty = tid >> 5;
#pragma unroll
    for (int i = 0; i < 32; i += 8)
        t[ty + i][tx] = in[(size_t)(k0 + ty + i) * N + n0 + tx];
    __syncthreads();
#pragma unroll
    for (int i = 0; i < 32; i += 8)
        out[(size_t)(n0 + ty + i) * K + k0 + tx] = __float2bfloat16(t[tx][ty + i]);
}

// ---------------- LayerNorm1 + shift + window partition ------------------------
__global__ __launch_bounds__(256)
void ln_kernel(const float* __restrict__ x, const float* __restrict__ g,
               const float* __restrict__ b, __nv_bfloat16* __restrict__ out)
{
    const int t = blockIdx.x * 8 + (threadIdx.x >> 5);
    const int lane = threadIdx.x & 31;
    const int b_ = t >> 6, n = t & 63;
    const int bb = b_ >> 9, widx = b_ & 511;
    const int hs = ((widx >> 6) << 2) + (n >> 4);
    const int ws = (((widx >> 3) & 7) << 2) + ((n >> 2) & 3);
    const int ds = ((widx & 7) << 2) + (n & 3);
    const size_t src = ((((size_t)bb * 32 + ((hs + 2) & 31)) * 32 + ((ws + 2) & 31)) * 32
                       + ((ds + 2) & 31));
    const float* xp = x + src * 192;
    float v[6];
    float s = 0.f;
#pragma unroll
    for (int r = 0; r < 6; ++r) { v[r] = xp[lane + 32 * r]; s += v[r]; }
#pragma unroll
    for (int o = 16; o > 0; o >>= 1) s += __shfl_xor_sync(0xffffffffu, s, o);
    const float mean = s * (1.f / 192.f);
    float vv = 0.f;
#pragma unroll
    for (int r = 0; r < 6; ++r) { const float d = v[r] - mean; vv += d * d; }
#pragma unroll
    for (int o = 16; o > 0; o >>= 1) vv += __shfl_xor_sync(0xffffffffu, vv, o);
    const float rstd = rsqrtf(vv * (1.f / 192.f) + 1e-5f);
    __nv_bfloat16* op = out + (size_t)t * 192;
#pragma unroll
    for (int r = 0; r < 6; ++r) {
        const int c = lane + 32 * r;
        op[c] = __float2bfloat16((v[r] - mean) * rstd * g[c] + b[c]);
    }
}

// ---------------- bf16 GEMM: BM=64, BN=192, BK=64, 2-stage double buffer -------
#define GSM_A 9216
#define GSM_B 27648
#define GSM_ST (GSM_A + GSM_B)
#define GSM_TOT (2 * GSM_ST)

template <int EPI>
__global__ __launch_bounds__(256, 3)
void mma_gemm(const __nv_bfloat16* __restrict__ A, const __nv_bfloat16* __restrict__ Bt,
              const float* __restrict__ bias, void* __restrict__ Cv,
              int K, int ldc, const float* __restrict__ resid,
              const float* __restrict__ lg, const float* __restrict__ lb,
              __nv_bfloat16* __restrict__ xn2)
{
    constexpr bool OBF = (EPI == 0 || EPI == 1);
    extern __shared__ __align__(16) uint8_t dsm[];
    __shared__ float2 red[64][4];

    const int tid = threadIdx.x;
    const int warp = tid >> 5, lane = tid & 31;
    const int m0 = blockIdx.y << 6;
    const int n0 = blockIdx.x * 192;
    const int mwarp = (warp & 1) << 5;
    const int nwarp = (warp >> 1) * 48;
    const uint32_t sb = smem_u32(dsm);
    const int lrow = lane & 15, lkh = lane >> 4;
    const int NC = K >> 6;

    auto issue = [&](int c) {
        if (c < NC) {
            const uint32_t ab = sb + (c & 1) * GSM_ST;
            const uint32_t bb = ab + GSM_A;
            const int kc = c << 6;
#pragma unroll
            for (int i = 0; i < 2; ++i) {
                const int idx = i * 256 + tid;
                const int row = idx >> 3, seg = idx & 7;
                cpa16(ab + row * 144 + seg * 16,
                      A + (size_t)(m0 + row) * K + kc + seg * 8);
            }
#pragma unroll
            for (int i = 0; i < 6; ++i) {
                const int idx = i * 256 + tid;
                const int row = idx >> 3, seg = idx & 7;
                cpa16(bb + row * 144 + seg * 16,
                      Bt + (size_t)(n0 + row) * K + kc + seg * 8);
            }
        }
        asm volatile("cp.async.commit_group;" ::: "memory");
    };

    float acc[2][6][4];
#pragma unroll
    for (int i = 0; i < 2; ++i)
#pragma unroll
        for (int j = 0; j < 6; ++j)
#pragma unroll
            for (int e = 0; e < 4; ++e) acc[i][j][e] = 0.f;

    issue(0);
    for (int c = 0; c < NC; ++c) {
        asm volatile("cp.async.wait_group 0;" ::: "memory");
        __syncthreads();
        issue(c + 1);
        const uint32_t ab = sb + (c & 1) * GSM_ST;
        const uint32_t bb = ab + GSM_A;
#pragma unroll
        for (int kk = 0; kk < 4; ++kk) {
            uint32_t a[2][4], b[3][4];
#pragma unroll
            for (int mi = 0; mi < 2; ++mi)
                ldsm_x4(a[mi], ab + (mwarp + mi * 16 + lrow) * 144 + kk * 32 + lkh * 16);
#pragma unroll
            for (int ng = 0; ng < 3; ++ng)
                ldsm_x4(b[ng], bb + (nwarp + ng * 16 + lrow) * 144 + kk * 32 + lkh * 16);
#pragma unroll
            for (int mi = 0; mi < 2; ++mi)
#pragma unroll
                for (int nj = 0; nj < 6; ++nj)
                    mma_bf16(acc[mi][nj], a[mi],
                             b[nj >> 1][nj & 1], b[nj >> 1][(nj & 1) + 2]);
        }
    }

    const int g = lane >> 2, t2 = (lane & 3) * 2;

    if (EPI == 2) {
        size_t tds[2][2];
#pragma unroll
        for (int mi = 0; mi < 2; ++mi) {
#pragma unroll
            for (int half = 0; half < 2; ++half) {
                const int r = mwarp + mi * 16 + g + half * 8;
                const int m = m0 + r;
                const int b_ = m >> 6, n = m & 63;
                const int bb2 = b_ >> 9, widx = b_ & 511;
                const int hs = ((widx >> 6) << 2) + (n >> 4);
                const int ws = (((widx >> 3) & 7) << 2) + ((n >> 2) & 3);
                const int ds = ((widx & 7) << 2) + (n & 3);
                const size_t td = ((((size_t)bb2 * 32 + ((hs + 2) & 31)) * 32
                                   + ((ws + 2) & 31)) * 32 + ((ds + 2) & 31));
                tds[mi][half] = td;
                float s = 0.f, sq = 0.f;
#pragma unroll
                for (int nj = 0; nj < 6; ++nj) {
                    const int col = nwarp + nj * 8 + t2;
                    const float2 bv = *(const float2*)(bias + col);
                    const float2 rv = *(const float2*)(resid + td * 192 + col);
                    float ox = acc[mi][nj][half * 2 + 0] + bv.x + rv.x;
                    float oy = acc[mi][nj][half * 2 + 1] + bv.y + rv.y;
                    acc[mi][nj][half * 2 + 0] = ox;
                    acc[mi][nj][half * 2 + 1] = oy;
                    *(float2*)((float*)Cv + td * 192 + col) = make_float2(ox, oy);
                    s += ox + oy;
                    sq += ox * ox + oy * oy;
                }
                s  += __shfl_xor_sync(0xffffffffu, s, 1);
                s  += __shfl_xor_sync(0xffffffffu, s, 2);
                sq += __shfl_xor_sync(0xffffffffu, sq, 1);
                sq += __shfl_xor_sync(0xffffffffu, sq, 2);
                if ((lane & 3) == 0) red[r][warp >> 1] = make_float2(s, sq);
            }
        }
        __syncthreads();
#pragma unroll
        for (int mi = 0; mi < 2; ++mi) {
#pragma unroll
            for (int half = 0; half < 2; ++half) {
                const int r = mwarp + mi * 16 + g + half * 8;
                const float2 r0 = red[r][0], r1 = red[r][1];
                const float2 r2 = red[r][2], r3 = red[r][3];
                const float s = r0.x + r1.x + r2.x + r3.x;
                const float sq = r0.y + r1.y + r2.y + r3.y;
                const float mean = s * (1.f / 192.f);
                const float var = sq * (1.f / 192.f) - mean * mean;
                const float rstd = rsqrtf(var + 1e-5f);
                const size_t td = tds[mi][half];
#pragma unroll
                for (int nj = 0; nj < 6; ++nj) {
                    const int col = nwarp + nj * 8 + t2;
                    const float2 gv = *(const float2*)(lg + col);
                    const float2 bv2 = *(const float2*)(lb + col);
                    const float vx = (acc[mi][nj][half * 2 + 0] - mean) * rstd * gv.x + bv2.x;
                    const float vy = (acc[mi][nj][half * 2 + 1] - mean) * rstd * gv.y + bv2.y;
                    *(uint32_t*)(xn2 + td * 192 + col) = pack_bf16(vx, vy);
                }
            }
        }
        return;
    }

#pragma unroll
    for (int mi = 0; mi < 2; ++mi) {
#pragma unroll
        for (int half = 0; half < 2; ++half) {
            const int m = m0 + mwarp + mi * 16 + g + half * 8;
#pragma unroll
            for (int nj = 0; nj < 6; ++nj) {
                const int col = n0 + nwarp + nj * 8 + t2;
                const float2 bv = *(const float2*)(bias + col);
                float ox = acc[mi][nj][half * 2 + 0] + bv.x;
                float oy = acc[mi][nj][half * 2 + 1] + bv.y;
                if (EPI == 1) {
                    const float kk = 0.70710678118654752f;
                    ox = 0.5f * ox * (1.f + erff(ox * kk));
                    oy = 0.5f * oy * (1.f + erff(oy * kk));
                }
                if (EPI == 3) {
                    const float2 rv = *(const float2*)(resid + (size_t)m * 192 + col);
                    ox += rv.x; oy += rv.y;
                }
                if (OBF) {
                    *(uint32_t*)((__nv_bfloat16*)Cv + (size_t)m * ldc + col) = pack_bf16(ox, oy);
                } else {
                    *(float2*)((float*)Cv + (size_t)m * ldc + col) = make_float2(ox, oy);
                }
            }
        }
    }
}

// ---------------- windowed attention (R12 configuration) -----------------------
__global__ __launch_bounds__(256)
void attn_kernel(const __nv_bfloat16* __restrict__ qkv, const __nv_bfloat16* __restrict__ bm,
                 __nv_bfloat16* __restrict__ out)
{
    __shared__ __align__(16) uint8_t qs[64 * 144];
    __shared__ __align__(16) uint8_t ks[64 * 144];
    __shared__ __align__(16) uint8_t vs[64 * 144];

    const int tid = threadIdx.x;
    const int wnd = blockIdx.x & 1023;
    const int hb = (blockIdx.x >> 10) << 1;
    const int widx = wnd & 511;
    const int wtype = (((widx >> 6) == 7) << 2) | ((((widx >> 3) & 7) == 7) << 1)
                    | ((widx & 7) == 7);

    {
        const int r = tid >> 2, s4 = tid & 3;
        const __nv_bfloat16* tp = qkv + ((size_t)wnd * 64 + r) * 576 + hb * 32;
        *(uint4*)(qs + r * 144 + s4 * 16)       = *(const uint4*)(tp + s4 * 8);
        *(uint4*)(qs + r * 144 + s4 * 16 + 64)  = *(const uint4*)(tp + s4 * 8 + 32);
        *(uint4*)(ks + r * 144 + s4 * 16)       = *(const uint4*)(tp + 192 + s4 * 8);
        *(uint4*)(ks + r * 144 + s4 * 16 + 64)  = *(const uint4*)(tp + 192 + s4 * 8 + 32);
        *(uint4*)(vs + r * 144 + s4 * 16)       = *(const uint4*)(tp + 384 + s4 * 8);
        *(uint4*)(vs + r * 144 + s4 * 16 + 64)  = *(const uint4*)(tp + 384 + s4 * 8 + 32);
    }
    __syncthreads();

    const int warp = tid >> 5, lane = tid & 31;
    const int lrow = lane & 15, lkh = lane >> 4;
    const int g = lane >> 2, t2 = (lane & 3) * 2;
    const int h = hb + (warp >> 2);
    const int hoff = (warp >> 2) * 64;
    const int msl = (warp & 3) * 16;
    const uint32_t qs_b = smem_u32(qs), ks_b = smem_u32(ks), vs_b = smem_u32(vs);
    const float scl = 0.17677669529663687f;

    float acc[8][4];
#pragma unroll
    for (int nj = 0; nj < 8; ++nj)
#pragma unroll
        for (int e = 0; e < 4; ++e) acc[nj][e] = 0.f;
#pragma unroll
    for (int kk = 0; kk < 2; ++kk) {
        uint32_t a[4];
        ldsm_x4(a, qs_b + (msl + lrow) * 144 + hoff + kk * 32 + lkh * 16);
#pragma unroll
        for (int ng = 0; ng < 4; ++ng) {
            uint32_t b[4];
            ldsm_x4(b, ks_b + (ng * 16 + lrow) * 144 + hoff + kk * 32 + lkh * 16);
            mma_bf16(acc[2 * ng],     a, b[0], b[2]);
            mma_bf16(acc[2 * ng + 1], a, b[1], b[3]);
        }
    }

    const int i0 = msl + g, i1 = i0 + 8;
    const __nv_bfloat16* bmp = bm + ((((size_t)h << 3) + wtype) << 12);
#pragma unroll
    for (int nj = 0; nj < 8; ++nj) {
        const int j = nj * 8 + t2;
        const float2 f0 = bf2f(*(const uint32_t*)(bmp + (i0 << 6) + j));
        const float2 f1 = bf2f(*(const uint32_t*)(bmp + (i1 << 6) + j));
        acc[nj][0] = fmaf(acc[nj][0], scl, f0.x);
        acc[nj][1] = fmaf(acc[nj][1], scl, f0.y);
        acc[nj][2] = fmaf(acc[nj][2], scl, f1.x);
        acc[nj][3] = fmaf(acc[nj][3], scl, f1.y);
    }

    float mx0 = -1e30f, mx1 = -1e30f;
#pragma unroll
    for (int nj = 0; nj < 8; ++nj) {
        mx0 = fmaxf(mx0, fmaxf(acc[nj][0], acc[nj][1]));
        mx1 = fmaxf(mx1, fmaxf(acc[nj][2], acc[nj][3]));
    }
    mx0 = fmaxf(mx0, __shfl_xor_sync(0xffffffffu, mx0, 1));
    mx0 = fmaxf(mx0, __shfl_xor_sync(0xffffffffu, mx0, 2));
    mx1 = fmaxf(mx1, __shfl_xor_sync(0xffffffffu, mx1, 1));
    mx1 = fmaxf(mx1, __shfl_xor_sync(0xffffffffu, mx1, 2));
    float s0 = 0.f, s1 = 0.f;
#pragma unroll
    for (int nj = 0; nj < 8; ++nj) {
        acc[nj][0] = __expf(acc[nj][0] - mx0); s0 += acc[nj][0];
        acc[nj][1] = __expf(acc[nj][1] - mx0); s0 += acc[nj][1];
        acc[nj][2] = __expf(acc[nj][2] - mx1); s1 += acc[nj][2];
        acc[nj][3] = __expf(acc[nj][3] - mx1); s1 += acc[nj][3];
    }
    s0 += __shfl_xor_sync(0xffffffffu, s0, 1);
    s0 += __shfl_xor_sync(0xffffffffu, s0, 2);
    s1 += __shfl_xor_sync(0xffffffffu, s1, 1);
    s1 += __shfl_xor_sync(0xffffffffu, s1, 2);
    const float r0 = 1.f / s0, r1 = 1.f / s1;

    uint32_t pa[4][4];
#pragma unroll
    for (int kc = 0; kc < 4; ++kc) {
        pa[kc][0] = pack_bf16(acc[2 * kc][0] * r0,     acc[2 * kc][1] * r0);
        pa[kc][1] = pack_bf16(acc[2 * kc][2] * r1,     acc[2 * kc][3] * r1);
        pa[kc][2] = pack_bf16(acc[2 * kc + 1][0] * r0, acc[2 * kc + 1][1] * r0);
        pa[kc][3] = pack_bf16(acc[2 * kc + 1][2] * r1, acc[2 * kc + 1][3] * r1);
    }
    float o[4][4];
#pragma unroll
    for (int dj = 0; dj < 4; ++dj)
#pragma unroll
        for (int e = 0; e < 4; ++e) o[dj][e] = 0.f;
#pragma unroll
    for (int kc = 0; kc < 4; ++kc) {
#pragma unroll
        for (int dt = 0; dt < 2; ++dt) {
            uint32_t b[4];
            ldsm_x4t(b, vs_b + (kc * 16 + lrow) * 144 + hoff + dt * 32 + lkh * 16);
            mma_bf16(o[2 * dt],     pa[kc], b[0], b[1]);
            mma_bf16(o[2 * dt + 1], pa[kc], b[2], b[3]);
        }
    }

#pragma unroll
    for (int dj = 0; dj < 4; ++dj) {
        const int d = dj * 8 + t2;
        __nv_bfloat16* op0 = out + ((size_t)wnd * 64 + i0) * 192 + h * 32 + d;
        *(uint32_t*)op0             = pack_bf16(o[dj][0], o[dj][1]);
        *(uint32_t*)(op0 + 8 * 192) = pack_bf16(o[dj][2], o[dj][3]);
    }
}

// ---------------- launch --------------------------------------------------------
extern "C" void kernel_launch(void* const* d_in, const int* in_sizes, int n_in,
                              void* d_out, int out_size)
{
    const float* x    = (const float*)d_in[0];
    const float* g1   = (const float*)d_in[1];
    const float* b1   = (const float*)d_in[2];
    const float* wqkv = (const float*)d_in[3];
    const float* bqkv = (const float*)d_in[4];
    const float* wo   = (const float*)d_in[5];
    const float* bo   = (const float*)d_in[6];
    const float* bt   = (const float*)d_in[7];
    const float* g2   = (const float*)d_in[8];
    const float* b2   = (const float*)d_in[9];
    const float* w1   = (const float*)d_in[10];
    const float* bm1  = (const float*)d_in[11];
    const float* w2   = (const float*)d_in[12];
    const float* bm2  = (const float*)d_in[13];
    float* out = (float*)d_out;

    __nv_bfloat16 *p_xw, *p_qkv, *p_attn, *p_xn2, *p_h1, *p_bm;
    __nv_bfloat16 *p_wqkvt, *p_wot, *p_w1t, *p_w2t;
    float *p_xo;
    cudaGetSymbolAddress((void**)&p_xw,    g_xw);
    cudaGetSymbolAddress((void**)&p_qkv,   g_qkv);
    cudaGetSymbolAddress((void**)&p_attn,  g_attn);
    cudaGetSymbolAddress((void**)&p_xo,    g_xo);
    cudaGetSymbolAddress((void**)&p_xn2,   g_xn2);
    cudaGetSymbolAddress((void**)&p_h1,    g_h1);
    cudaGetSymbolAddress((void**)&p_wqkvt, g_wqkvt);
    cudaGetSymbolAddress((void**)&p_wot,   g_wot);
    cudaGetSymbolAddress((void**)&p_w1t,   g_w1t);
    cudaGetSymbolAddress((void**)&p_w2t,   g_w2t);
    cudaGetSymbolAddress((void**)&p_bm,    g_bm);

    cudaFuncSetAttribute(mma_gemm<0>, cudaFuncAttributeMaxDynamicSharedMemorySize, GSM_TOT);
    cudaFuncSetAttribute(mma_gemm<1>, cudaFuncAttributeMaxDynamicSharedMemorySize, GSM_TOT);
    cudaFuncSetAttribute(mma_gemm<2>, cudaFuncAttributeMaxDynamicSharedMemorySize, GSM_TOT);
    cudaFuncSetAttribute(mma_gemm<3>, cudaFuncAttributeMaxDynamicSharedMemorySize, GSM_TOT);

    prep_kernel<<<1200, 256>>>(wqkv, p_wqkvt, wo, p_wot, w1, p_w1t, w2, p_w2t, bt, p_bm);
    ln_kernel<<<NTOK / 8, 256>>>(x, g1, b1, p_xw);
    mma_gemm<0><<<dim3(3, NTOK / 64), 256, GSM_TOT>>>(p_xw, p_wqkvt, bqkv, p_qkv,
                                                      192, 576, nullptr, nullptr, nullptr, nullptr);
    attn_kernel<<<3072, 256>>>(p_qkv, p_bm, p_attn);
    mma_gemm<2><<<dim3(1, NTOK / 64), 256, GSM_TOT>>>(p_attn, p_wot, bo, p_xo,
                                                      192, 192, x, g2, b2, p_xn2);
    mma_gemm<1><<<dim3(4, NTOK / 64), 256, GSM_TOT>>>(p_xn2, p_w1t, bm1, p_h1,
                                                      192, 768, nullptr, nullptr, nullptr, nullptr);
    mma_gemm<3><<<dim3(1, NTOK / 64), 256, GSM_TOT>>>(p_h1, p_w2t, bm2, out,
                                                      768, 192, p_xo, nullptr, nullptr, nullptr);
}